// round 1
// baseline (speedup 1.0000x reference)
#include <cuda_runtime.h>
#include <math.h>

// Fixed problem shape (from reference): B=8192, H=512, M=4096, D=256, k<=32
#define BN 8192
#define MN 4096
#define DN 256
#define HN 512
#define MAXK 32
#define BIGF 3.0e37f

// Scratch (device globals — no allocation allowed in kernel_launch)
__device__ float g_q[BN * DN];          // 8 MB   : q projection
__device__ float g_qsq[BN];             //        : ||q||^2 per row
__device__ float g_msq[MN];             //        : ||m||^2 per memory slot
__device__ float g_dist[(size_t)BN * MN]; // 134 MB : full distance matrix

// ---------------------------------------------------------------------------
// Kernel 1: q = h @ Wq + bq       (NN gemm: h [B,H] k-major, Wq [H,D] row-major)
// 128x128 tile, 8x8 microtile, 256 threads, KC=8
// ---------------------------------------------------------------------------
__global__ __launch_bounds__(256, 2)
void qproj_kernel(const float* __restrict__ Hm, const float* __restrict__ Wq,
                  const float* __restrict__ bq, int B, int Hd, int D) {
    __shared__ float As[8][128];   // As[k][row]   (h tile, transposed store)
    __shared__ float Bs[8][128];   // Bs[k][col]   (Wq tile, direct store)

    const int tid  = threadIdx.x;
    const int brow = blockIdx.y * 128;
    const int bcol = blockIdx.x * 128;
    const int tx = tid & 15, ty = tid >> 4;

    // A loads: 128 rows x 8 k -> 256 float4 loads (2 per row)
    const int a_row = tid >> 1;
    const int a_k   = (tid & 1) * 4;
    // B loads: 8 k-rows x 128 cols -> 256 float4 loads (32 per k-row)
    const int b_k = tid >> 5;
    const int b_c = (tid & 31) * 4;

    const float* Ap = Hm + (size_t)(brow + a_row) * Hd + a_k;
    const float* Bp = Wq + (size_t)b_k * D + bcol + b_c;

    float acc[8][8];
#pragma unroll
    for (int i = 0; i < 8; i++)
#pragma unroll
        for (int j = 0; j < 8; j++) acc[i][j] = 0.f;

    for (int k0 = 0; k0 < Hd; k0 += 8) {
        float4 av = *(const float4*)(Ap + k0);
        float4 bv = *(const float4*)(Bp + (size_t)k0 * D);
        __syncthreads();
        As[a_k + 0][a_row] = av.x; As[a_k + 1][a_row] = av.y;
        As[a_k + 2][a_row] = av.z; As[a_k + 3][a_row] = av.w;
        *(float4*)&Bs[b_k][b_c] = bv;
        __syncthreads();
#pragma unroll
        for (int kk = 0; kk < 8; kk++) {
            float ar[8], br[8];
            *(float4*)&ar[0] = *(const float4*)&As[kk][ty * 8];
            *(float4*)&ar[4] = *(const float4*)&As[kk][ty * 8 + 4];
            *(float4*)&br[0] = *(const float4*)&Bs[kk][tx * 8];
            *(float4*)&br[4] = *(const float4*)&Bs[kk][tx * 8 + 4];
#pragma unroll
            for (int i = 0; i < 8; i++)
#pragma unroll
                for (int j = 0; j < 8; j++) acc[i][j] += ar[i] * br[j];
        }
    }

#pragma unroll
    for (int i = 0; i < 8; i++) {
        int r = brow + ty * 8 + i;
#pragma unroll
        for (int j = 0; j < 8; j += 4) {
            int c = bcol + tx * 8 + j;
            float4 o;
            o.x = acc[i][j + 0] + bq[c + 0];
            o.y = acc[i][j + 1] + bq[c + 1];
            o.z = acc[i][j + 2] + bq[c + 2];
            o.w = acc[i][j + 3] + bq[c + 3];
            *(float4*)&g_q[(size_t)r * D + c] = o;
        }
    }
}

// ---------------------------------------------------------------------------
// Row squared norms
// ---------------------------------------------------------------------------
__global__ void qsq_kernel(int D) {
    const int r = blockIdx.x;
    const float4* p = (const float4*)(g_q + (size_t)r * D);
    float s = 0.f;
    for (int i = threadIdx.x; i < D / 4; i += 64) {
        float4 v = p[i];
        s += v.x * v.x + v.y * v.y + v.z * v.z + v.w * v.w;
    }
#pragma unroll
    for (int off = 16; off; off >>= 1) s += __shfl_down_sync(0xffffffffu, s, off);
    __shared__ float ws[2];
    if ((threadIdx.x & 31) == 0) ws[threadIdx.x >> 5] = s;
    __syncthreads();
    if (threadIdx.x == 0) g_qsq[r] = ws[0] + ws[1];
}

__global__ void msq_kernel(const float* __restrict__ Mem, int D) {
    const int r = blockIdx.x;
    const float4* p = (const float4*)(Mem + (size_t)r * D);
    float s = 0.f;
    for (int i = threadIdx.x; i < D / 4; i += 64) {
        float4 v = p[i];
        s += v.x * v.x + v.y * v.y + v.z * v.z + v.w * v.w;
    }
#pragma unroll
    for (int off = 16; off; off >>= 1) s += __shfl_down_sync(0xffffffffu, s, off);
    __shared__ float ws[2];
    if ((threadIdx.x & 31) == 0) ws[threadIdx.x >> 5] = s;
    __syncthreads();
    if (threadIdx.x == 0) g_msq[r] = ws[0] + ws[1];
}

// ---------------------------------------------------------------------------
// Kernel 3: dist[b,m] = qsq[b] + msq[m] - 2 * (q_b . mem_m)
// NT gemm (both operands K-major). 128x128 tile, 8x8 micro, 256 threads.
// ---------------------------------------------------------------------------
__global__ __launch_bounds__(256, 2)
void dist_kernel(const float* __restrict__ Mem, int B, int M, int D) {
    __shared__ float As[8][128];   // q tile,   As[k][row]
    __shared__ float Bs[8][128];   // mem tile, Bs[k][col]

    const int tid  = threadIdx.x;
    const int brow = blockIdx.y * 128;   // over B
    const int bcol = blockIdx.x * 128;   // over M
    const int tx = tid & 15, ty = tid >> 4;

    const int a_row = tid >> 1;
    const int a_k   = (tid & 1) * 4;

    const float* Ap = g_q + (size_t)(brow + a_row) * D + a_k;
    const float* Bp = Mem + (size_t)(bcol + a_row) * D + a_k;

    float acc[8][8];
#pragma unroll
    for (int i = 0; i < 8; i++)
#pragma unroll
        for (int j = 0; j < 8; j++) acc[i][j] = 0.f;

    for (int k0 = 0; k0 < D; k0 += 8) {
        float4 av = *(const float4*)(Ap + k0);
        float4 bv = *(const float4*)(Bp + k0);
        __syncthreads();
        As[a_k + 0][a_row] = av.x; As[a_k + 1][a_row] = av.y;
        As[a_k + 2][a_row] = av.z; As[a_k + 3][a_row] = av.w;
        Bs[a_k + 0][a_row] = bv.x; Bs[a_k + 1][a_row] = bv.y;
        Bs[a_k + 2][a_row] = bv.z; Bs[a_k + 3][a_row] = bv.w;
        __syncthreads();
#pragma unroll
        for (int kk = 0; kk < 8; kk++) {
            float ar[8], br[8];
            *(float4*)&ar[0] = *(const float4*)&As[kk][ty * 8];
            *(float4*)&ar[4] = *(const float4*)&As[kk][ty * 8 + 4];
            *(float4*)&br[0] = *(const float4*)&Bs[kk][tx * 8];
            *(float4*)&br[4] = *(const float4*)&Bs[kk][tx * 8 + 4];
#pragma unroll
            for (int i = 0; i < 8; i++)
#pragma unroll
                for (int j = 0; j < 8; j++) acc[i][j] += ar[i] * br[j];
        }
    }

#pragma unroll
    for (int i = 0; i < 8; i++) {
        int r = brow + ty * 8 + i;
        float qs = g_qsq[r];
#pragma unroll
        for (int j = 0; j < 8; j += 4) {
            int c = bcol + tx * 8 + j;
            float4 o;
            o.x = qs + g_msq[c + 0] - 2.f * acc[i][j + 0];
            o.y = qs + g_msq[c + 1] - 2.f * acc[i][j + 1];
            o.z = qs + g_msq[c + 2] - 2.f * acc[i][j + 2];
            o.w = qs + g_msq[c + 3] - 2.f * acc[i][j + 3];
            *(float4*)&g_dist[(size_t)r * M + c] = o;
        }
    }
}

// ---------------------------------------------------------------------------
// Kernel 4: per row b — top-k smallest distances (tournament argmin), softmax
// of negated values, gather+weighted-sum of memory embeddings.
// One block (128 threads) per row.
// ---------------------------------------------------------------------------
__global__ __launch_bounds__(128)
void topk_kernel(const float* __restrict__ Mem, const int* __restrict__ kp,
                 float* __restrict__ out, int M, int D) {
    const int b   = blockIdx.x;
    const int tid = threadIdx.x;
    int k = kp[0];
    if (k < 1) k = 1;
    if (k > MAXK) k = MAXK;

    __shared__ float sd[MN];       // full distance row (16 KB)
    __shared__ float tval[128];    // per-thread local min value
    __shared__ int   tidxs[128];   // per-thread local min index
    __shared__ float swt[MAXK];    // selected distances -> weights
    __shared__ int   sel[MAXK];    // selected memory indices
    __shared__ int   swin;         // winning thread slot per round

    // Load distance row into smem (coalesced float4)
    const float4* rp = (const float4*)(g_dist + (size_t)b * M);
    for (int i = tid; i < M / 4; i += 128) ((float4*)sd)[i] = rp[i];
    __syncthreads();

    // Per-thread local argmin over strided slice
    float bv = BIGF; int bi = -1;
    for (int i = tid; i < M; i += 128) {
        float v = sd[i];
        if (v < bv) { bv = v; bi = i; }
    }
    tval[tid] = bv; tidxs[tid] = bi;
    __syncthreads();

    // k rounds: global argmin over 128 candidates; loser rescans its slice
    for (int it = 0; it < k; it++) {
        if (tid < 32) {
            float v = tval[tid]; int slot = tid;
#pragma unroll
            for (int s = 32; s < 128; s += 32) {
                float v2 = tval[tid + s];
                if (v2 < v) { v = v2; slot = tid + s; }
            }
#pragma unroll
            for (int off = 16; off; off >>= 1) {
                float v2  = __shfl_down_sync(0xffffffffu, v, off);
                int   sl2 = __shfl_down_sync(0xffffffffu, slot, off);
                if (v2 < v) { v = v2; slot = sl2; }
            }
            if (tid == 0) {
                swin    = slot;
                swt[it] = v;
                sel[it] = tidxs[slot];
            }
        }
        __syncthreads();
        if (tid == swin) {
            sd[tidxs[tid]] = BIGF;          // remove selected
            float nv = BIGF; int ni = -1;   // rescan my slice
            for (int i = tid; i < M; i += 128) {
                float v = sd[i];
                if (v < nv) { nv = v; ni = i; }
            }
            tval[tid] = nv; tidxs[tid] = ni;
        }
        __syncthreads();
    }

    // softmax(-dist) over the k selected (swt[0] is the min distance)
    if (tid == 0) {
        float d0 = swt[0];
        float s = 0.f;
        for (int i = 0; i < k; i++) {
            float e = expf(d0 - swt[i]);
            swt[i] = e;
            s += e;
        }
        float inv = 1.f / s;
        for (int i = 0; i < k; i++) swt[i] *= inv;
    }
    __syncthreads();

    // weighted gather: out[b,d] = sum_i w_i * Mem[sel_i, d]
    for (int d = tid; d < D; d += 128) {
        float acc = 0.f;
        for (int i = 0; i < k; i++)
            acc += swt[i] * Mem[(size_t)sel[i] * D + d];
        out[(size_t)b * D + d] = acc;
    }
}

// ---------------------------------------------------------------------------
extern "C" void kernel_launch(void* const* d_in, const int* in_sizes, int n_in,
                              void* d_out, int out_size) {
    const float* h   = (const float*)d_in[0];
    const float* mem = (const float*)d_in[1];
    const float* Wq  = (const float*)d_in[2];
    const float* bq  = (const float*)d_in[3];
    const int*   kp  = (const int*)d_in[4];
    float* out = (float*)d_out;

    const int D  = in_sizes[3];            // 256
    const int Hd = in_sizes[2] / D;        // 512
    const int B  = in_sizes[0] / Hd;       // 8192
    const int M  = in_sizes[1] / D;        // 4096

    dim3 g1(D / 128, B / 128);             // (2, 64)
    qproj_kernel<<<g1, 256>>>(h, Wq, bq, B, Hd, D);
    qsq_kernel<<<B, 64>>>(D);
    msq_kernel<<<M, 64>>>(mem, D);
    dim3 g3(M / 128, B / 128);             // (32, 64)
    dist_kernel<<<g3, 256>>>(mem, B, M, D);
    topk_kernel<<<B, 128>>>(mem, kp, out, M, D);
}

// round 6
// speedup vs baseline: 1.1618x; 1.1618x over previous
#include <cuda_runtime.h>
#include <cuda_bf16.h>
#include <mma.h>
#include <cstdint>
#include <math.h>

using namespace nvcuda;

// Problem shape: B=8192, H=512, M=4096, D=256, k<=32
#define BN 8192
#define MN 4096
#define DN 256
#define MAXK 32
#define NCAND 32
#define BIGF 3.0e37f

__device__ float g_q[BN * DN];               // exact fp32 q (for rescore)
__device__ __nv_bfloat16 g_qb[BN * DN];      // bf16 q (for WMMA)
__device__ __nv_bfloat16 g_mb[MN * DN];      // bf16 mem (for WMMA)
__device__ float g_msq[MN];                  // exact ||m||^2
__device__ float g_dist[(size_t)BN * MN];    // approx dists (selection only)

// ---------------------------------------------------------------------------
// Kernel 1: q = h @ Wq + bq  (exact fp32 SGEMM) + bf16 copy of q
// ---------------------------------------------------------------------------
__global__ __launch_bounds__(256, 2)
void qproj_kernel(const float* __restrict__ Hm, const float* __restrict__ Wq,
                  const float* __restrict__ bq, int B, int Hd, int D) {
    __shared__ float As[8][128];
    __shared__ float Bs[8][128];
    const int tid = threadIdx.x;
    const int brow = blockIdx.y * 128, bcol = blockIdx.x * 128;
    const int tx = tid & 15, ty = tid >> 4;
    const int a_row = tid >> 1, a_k = (tid & 1) * 4;
    const int b_k = tid >> 5, b_c = (tid & 31) * 4;
    const float* Ap = Hm + (size_t)(brow + a_row) * Hd + a_k;
    const float* Bp = Wq + (size_t)b_k * D + bcol + b_c;
    float acc[8][8];
#pragma unroll
    for (int i = 0; i < 8; i++)
#pragma unroll
        for (int j = 0; j < 8; j++) acc[i][j] = 0.f;
    for (int k0 = 0; k0 < Hd; k0 += 8) {
        float4 av = *(const float4*)(Ap + k0);
        float4 bv = *(const float4*)(Bp + (size_t)k0 * D);
        __syncthreads();
        As[a_k + 0][a_row] = av.x; As[a_k + 1][a_row] = av.y;
        As[a_k + 2][a_row] = av.z; As[a_k + 3][a_row] = av.w;
        *(float4*)&Bs[b_k][b_c] = bv;
        __syncthreads();
#pragma unroll
        for (int kk = 0; kk < 8; kk++) {
            float ar[8], br[8];
            *(float4*)&ar[0] = *(const float4*)&As[kk][ty * 8];
            *(float4*)&ar[4] = *(const float4*)&As[kk][ty * 8 + 4];
            *(float4*)&br[0] = *(const float4*)&Bs[kk][tx * 8];
            *(float4*)&br[4] = *(const float4*)&Bs[kk][tx * 8 + 4];
#pragma unroll
            for (int i = 0; i < 8; i++)
#pragma unroll
                for (int j = 0; j < 8; j++) acc[i][j] += ar[i] * br[j];
        }
    }
#pragma unroll
    for (int i = 0; i < 8; i++) {
        int r = brow + ty * 8 + i;
#pragma unroll
        for (int j = 0; j < 8; j += 4) {
            int c = bcol + tx * 8 + j;
            float4 o;
            o.x = acc[i][j + 0] + bq[c + 0];
            o.y = acc[i][j + 1] + bq[c + 1];
            o.z = acc[i][j + 2] + bq[c + 2];
            o.w = acc[i][j + 3] + bq[c + 3];
            *(float4*)&g_q[(size_t)r * D + c] = o;
            __nv_bfloat162 p0 = __float22bfloat162_rn(make_float2(o.x, o.y));
            __nv_bfloat162 p1 = __float22bfloat162_rn(make_float2(o.z, o.w));
            uint2 pk; pk.x = *(uint32_t*)&p0; pk.y = *(uint32_t*)&p1;
            *(uint2*)&g_qb[(size_t)r * D + c] = pk;
        }
    }
}

// ---------------------------------------------------------------------------
// msq (exact fp32) + bf16 copy of mem
// ---------------------------------------------------------------------------
__global__ void msq_kernel(const float* __restrict__ Mem, int D) {
    const int r = blockIdx.x;
    const float4* p = (const float4*)(Mem + (size_t)r * D);
    float s = 0.f;
    for (int i = threadIdx.x; i < D / 4; i += 64) {
        float4 v = p[i];
        s += v.x * v.x + v.y * v.y + v.z * v.z + v.w * v.w;
        __nv_bfloat162 p0 = __float22bfloat162_rn(make_float2(v.x, v.y));
        __nv_bfloat162 p1 = __float22bfloat162_rn(make_float2(v.z, v.w));
        uint2 pk; pk.x = *(uint32_t*)&p0; pk.y = *(uint32_t*)&p1;
        *(uint2*)&g_mb[(size_t)r * D + i * 4] = pk;
    }
#pragma unroll
    for (int off = 16; off; off >>= 1) s += __shfl_down_sync(0xffffffffu, s, off);
    __shared__ float ws[2];
    if ((threadIdx.x & 31) == 0) ws[threadIdx.x >> 5] = s;
    __syncthreads();
    if (threadIdx.x == 0) g_msq[r] = ws[0] + ws[1];
}

// ---------------------------------------------------------------------------
// Kernel 3: dist[b,m] ~= msq[m] - 2*(q_b . mem_m) via WMMA bf16 (NO inline asm).
// CTA 128x128, 8 warps (2 m x 4 n), warp tile 64x32 = 4x2 wmma 16x16x16 frags.
// Fragments loaded straight from gmem (per-k working set 8KB -> L1-resident).
// ---------------------------------------------------------------------------
__global__ __launch_bounds__(256, 2)
void dist_wmma_kernel(int B, int M, int D) {
    __shared__ float ebuf[8 * 256];   // per-warp 16x16 epilogue staging (8KB)
    __shared__ float msq_s[128];
    const int tid = threadIdx.x;
    const int lane = tid & 31, wid = tid >> 5;
    const int warp_m = wid >> 2, warp_n = wid & 3;     // 2 x 4
    const int brow = blockIdx.y * 128;                  // B rows
    const int bcol = blockIdx.x * 128;                  // M cols

    if (tid < 128) msq_s[tid] = g_msq[bcol + tid];
    __syncthreads();

    wmma::fragment<wmma::accumulator, 16, 16, 16, float> acc[4][2];
#pragma unroll
    for (int mt = 0; mt < 4; mt++)
#pragma unroll
        for (int nt = 0; nt < 2; nt++) wmma::fill_fragment(acc[mt][nt], 0.f);

    const __nv_bfloat16* Aw = g_qb + (size_t)(brow + warp_m * 64) * DN;
    const __nv_bfloat16* Bw = g_mb + (size_t)(bcol + warp_n * 32) * DN;

    for (int k = 0; k < DN; k += 16) {
        wmma::fragment<wmma::matrix_a, 16, 16, 16, __nv_bfloat16, wmma::row_major> af[4];
        wmma::fragment<wmma::matrix_b, 16, 16, 16, __nv_bfloat16, wmma::col_major> bf[2];
#pragma unroll
        for (int mt = 0; mt < 4; mt++)
            wmma::load_matrix_sync(af[mt], Aw + (size_t)mt * 16 * DN + k, DN);
#pragma unroll
        for (int nt = 0; nt < 2; nt++)
            wmma::load_matrix_sync(bf[nt], Bw + (size_t)nt * 16 * DN + k, DN);
#pragma unroll
        for (int mt = 0; mt < 4; mt++)
#pragma unroll
            for (int nt = 0; nt < 2; nt++)
                wmma::mma_sync(acc[mt][nt], af[mt], bf[nt], acc[mt][nt]);
    }

    // epilogue: stage each 16x16 frag through smem, apply msq[m] - 2*acc
    float* eb = ebuf + wid * 256;
    const int er = lane >> 1, ec = (lane & 1) * 8;
#pragma unroll
    for (int mt = 0; mt < 4; mt++) {
#pragma unroll
        for (int nt = 0; nt < 2; nt++) {
            wmma::store_matrix_sync(eb, acc[mt][nt], 16, wmma::mem_row_major);
            __syncwarp();
            int grow = brow + warp_m * 64 + mt * 16 + er;
            int cl = warp_n * 32 + nt * 16 + ec;      // local col in [0,128)
            const float* e = eb + er * 16 + ec;
            float4 o0, o1;
            o0.x = msq_s[cl + 0] - 2.f * e[0];
            o0.y = msq_s[cl + 1] - 2.f * e[1];
            o0.z = msq_s[cl + 2] - 2.f * e[2];
            o0.w = msq_s[cl + 3] - 2.f * e[3];
            o1.x = msq_s[cl + 4] - 2.f * e[4];
            o1.y = msq_s[cl + 5] - 2.f * e[5];
            o1.z = msq_s[cl + 6] - 2.f * e[6];
            o1.w = msq_s[cl + 7] - 2.f * e[7];
            *(float4*)&g_dist[(size_t)grow * M + bcol + cl] = o0;
            *(float4*)&g_dist[(size_t)grow * M + bcol + cl + 4] = o1;
            __syncwarp();
        }
    }
}

// ---------------------------------------------------------------------------
// Kernel 4: approx top-32 -> exact fp32 rescore -> exact top-k -> softmax ->
// weighted gather. One 128-thread block per row.
// ---------------------------------------------------------------------------
__global__ __launch_bounds__(128)
void topk_kernel(const float* __restrict__ Mem, const int* __restrict__ kp,
                 float* __restrict__ out, int M, int D) {
    const int b = blockIdx.x;
    const int tid = threadIdx.x;
    const int wid = tid >> 5, lane = tid & 31;
    int k = kp[0];
    if (k < 1) k = 1;
    if (k > NCAND) k = NCAND;

    __shared__ float sd[MN];
    __shared__ float sq[DN];
    __shared__ float tval[128];
    __shared__ int tidxs[128];
    __shared__ int cand[NCAND];
    __shared__ float cdist[NCAND];
    __shared__ float swt[MAXK];
    __shared__ int sel[MAXK];
    __shared__ int swin;

    const float4* rp = (const float4*)(g_dist + (size_t)b * M);
    for (int i = tid; i < M / 4; i += 128) ((float4*)sd)[i] = rp[i];
    for (int i = tid; i < D / 4; i += 128) ((float4*)sq)[i] = ((const float4*)(g_q + (size_t)b * D))[i];
    __syncthreads();

    float bv = BIGF; int bi = -1;
    for (int i = tid; i < M; i += 128) {
        float v = sd[i];
        if (v < bv) { bv = v; bi = i; }
    }
    tval[tid] = bv; tidxs[tid] = bi;
    __syncthreads();
    for (int it = 0; it < NCAND; it++) {
        if (tid < 32) {
            float v = tval[tid]; int slot = tid;
#pragma unroll
            for (int s = 32; s < 128; s += 32) {
                float v2 = tval[tid + s];
                if (v2 < v) { v = v2; slot = tid + s; }
            }
#pragma unroll
            for (int off = 16; off; off >>= 1) {
                float v2 = __shfl_down_sync(0xffffffffu, v, off);
                int sl2 = __shfl_down_sync(0xffffffffu, slot, off);
                if (v2 < v) { v = v2; slot = sl2; }
            }
            if (tid == 0) { swin = slot; cand[it] = tidxs[slot]; }
        }
        __syncthreads();
        if (tid == swin && tidxs[tid] >= 0) {
            sd[tidxs[tid]] = BIGF;
            float nv = BIGF; int ni = -1;
            for (int i = tid; i < M; i += 128) {
                float v = sd[i];
                if (v < nv) { nv = v; ni = i; }
            }
            tval[tid] = nv; tidxs[tid] = ni;
        }
        __syncthreads();
    }

    // exact rescore: dist = msq[c] - 2 * (q . mem_c)  (fp32)
    for (int i = 0; i < 8; i++) {
        int ci = wid * 8 + i;
        int midx = cand[ci];
        if (midx < 0) { if (lane == 0) cdist[ci] = BIGF; continue; }
        const float4* mp = (const float4*)(Mem + (size_t)midx * D + lane * 8);
        float4 m0 = mp[0], m1 = mp[1];
        float4 a0 = *(const float4*)&sq[lane * 8];
        float4 a1 = *(const float4*)&sq[lane * 8 + 4];
        float s = a0.x * m0.x + a0.y * m0.y + a0.z * m0.z + a0.w * m0.w
                + a1.x * m1.x + a1.y * m1.y + a1.z * m1.z + a1.w * m1.w;
#pragma unroll
        for (int off = 16; off; off >>= 1) s += __shfl_down_sync(0xffffffffu, s, off);
        if (lane == 0) cdist[ci] = g_msq[midx] - 2.f * s;
    }
    __syncthreads();

    if (tid < 32) {
        float v = cdist[tid];
        for (int it = 0; it < k; it++) {
            float m = v; int s = tid;
#pragma unroll
            for (int off = 16; off; off >>= 1) {
                float m2 = __shfl_xor_sync(0xffffffffu, m, off);
                int s2 = __shfl_xor_sync(0xffffffffu, s, off);
                if (m2 < m || (m2 == m && s2 < s)) { m = m2; s = s2; }
            }
            if (tid == 0) { swt[it] = m; sel[it] = cand[s]; }
            if (tid == s) v = BIGF;
        }
    }
    __syncthreads();

    if (tid == 0) {
        float d0 = swt[0], ssum = 0.f;
        for (int i = 0; i < k; i++) {
            float e = expf(d0 - swt[i]);
            swt[i] = e; ssum += e;
        }
        float inv = 1.f / ssum;
        for (int i = 0; i < k; i++) swt[i] *= inv;
    }
    __syncthreads();

    for (int d = tid; d < D; d += 128) {
        float acc = 0.f;
        for (int i = 0; i < k; i++)
            acc += swt[i] * Mem[(size_t)sel[i] * D + d];
        out[(size_t)b * D + d] = acc;
    }
}

// ---------------------------------------------------------------------------
extern "C" void kernel_launch(void* const* d_in, const int* in_sizes, int n_in,
                              void* d_out, int out_size) {
    const float* h   = (const float*)d_in[0];
    const float* mem = (const float*)d_in[1];
    const float* Wq  = (const float*)d_in[2];
    const float* bq  = (const float*)d_in[3];
    const int*   kp  = (const int*)d_in[4];
    float* out = (float*)d_out;

    const int D  = in_sizes[3];
    const int Hd = in_sizes[2] / D;
    const int B  = in_sizes[0] / Hd;
    const int M  = in_sizes[1] / D;

    dim3 g1(D / 128, B / 128);
    qproj_kernel<<<g1, 256>>>(h, Wq, bq, B, Hd, D);
    msq_kernel<<<M, 64>>>(mem, D);
    dim3 g3(M / 128, B / 128);
    dist_wmma_kernel<<<g3, 256>>>(B, M, D);
    topk_kernel<<<B, 128>>>(mem, kp, out, M, D);
}